// round 5
// baseline (speedup 1.0000x reference)
#include <cuda_runtime.h>
#include <cuda_fp16.h>
#include <cstdint>

// ---------------------------------------------------------------------------
// SmallMLP_INR: fused 6-layer MLP, base-target ISA (compute_103-safe).
// fp16 m16n8k16 mma.sync + ldmatrix. 64-row CTAs, 2 CTAs/SM so epilogues of
// one CTA overlap MMAs of the other. Warp-private double-buffered B chunks
// (XOR-swizzled 128B rows), no CTA barriers in the MMA loop.
// ---------------------------------------------------------------------------

#define THREADS 256
#define TILE_M  64
#define KDIM    256
#define NDIM    256

#define A_STRIDE 264   // halves; 528B rows -> ldmatrix conflict-free

// SMEM layout (bytes)
#define SM_W1    0        // 512 f32
#define SM_B1    2048
#define SM_B2    3072
#define SM_B3    4096
#define SM_B4    5120
#define SM_B5    6144
#define SM_W6    7168
#define SM_B6    8192
#define SM_PART  8208     // 8*64 f32 = 2048
#define SM_A     10496    // 64*264*2 = 33792
#define SM_B     44288    // 8 warps * 2 bufs * 4096 = 65536
#define SMEM_TOTAL 109824

// Pre-transposed fp16 weights: g_WtH[l][n*256 + k] = (half)W_{l+2}[k][n]
__device__ __half g_WtH[4][KDIM * NDIM];

// ---------------------------------------------------------------------------
__device__ __forceinline__ uint32_t smem_u32(const void* p) {
    uint32_t a;
    asm("{ .reg .u64 t; cvta.to.shared.u64 t, %1; cvt.u32.u64 %0, t; }" : "=r"(a) : "l"(p));
    return a;
}

__device__ __forceinline__ void mma_f16(float* c, const uint32_t* a, const uint32_t* b) {
    asm volatile(
        "mma.sync.aligned.m16n8k16.row.col.f32.f16.f16.f32 "
        "{%0,%1,%2,%3}, {%4,%5,%6,%7}, {%8,%9}, {%0,%1,%2,%3};\n"
        : "+f"(c[0]), "+f"(c[1]), "+f"(c[2]), "+f"(c[3])
        : "r"(a[0]), "r"(a[1]), "r"(a[2]), "r"(a[3]), "r"(b[0]), "r"(b[1]));
}

#define LDMATRIX_X4(r0, r1, r2, r3, addr) \
    asm volatile("ldmatrix.sync.aligned.m8n8.x4.shared.b16 {%0,%1,%2,%3}, [%4];" \
                 : "=r"(r0), "=r"(r1), "=r"(r2), "=r"(r3) : "r"(addr))

__device__ __forceinline__ void cp_async16(uint32_t dst, const void* src) {
    asm volatile("cp.async.cg.shared.global [%0], [%1], 16;" :: "r"(dst), "l"(src) : "memory");
}
__device__ __forceinline__ void cp_commit() { asm volatile("cp.async.commit_group;" ::: "memory"); }
__device__ __forceinline__ void cp_wait1()  { asm volatile("cp.async.wait_group 1;" ::: "memory"); }
__device__ __forceinline__ void cp_wait0()  { asm volatile("cp.async.wait_group 0;" ::: "memory"); }

// Warp-private B chunk buffer: 32 rows x 128B, XOR-swizzled 16B segments.
// lane r loads N-row (nbase+r), k in [64c, 64c+64): 8 x 16B cp.async.
__device__ __forceinline__ void load_wchunk(uint32_t buf, const __half* Wt,
                                            int nbase, int c, int lane) {
    const uint32_t dstrow = buf + (uint32_t)lane * 128;
    const uint32_t rx = (uint32_t)(lane & 7);
    const __half* src = Wt + (size_t)(nbase + lane) * KDIM + c * 64;
#pragma unroll
    for (uint32_t j = 0; j < 8; j++)
        cp_async16(dstrow + ((j ^ rx) << 4), src + j * 8);
    cp_commit();
}

// ---------------------------------------------------------------------------
// weight pre-transpose + fp16 round
// ---------------------------------------------------------------------------
__global__ void transpose_w_kernel(const float* __restrict__ W2, const float* __restrict__ W3,
                                   const float* __restrict__ W4, const float* __restrict__ W5) {
    __shared__ float t[32][33];
    const float* W = (blockIdx.z == 0) ? W2 : (blockIdx.z == 1) ? W3
                   : (blockIdx.z == 2) ? W4 : W5;
    const int nb = blockIdx.x * 32, kb = blockIdx.y * 32;
    const int tx = threadIdx.x, ty = threadIdx.y;
#pragma unroll
    for (int i = 0; i < 32; i += 8)
        t[ty + i][tx] = W[(size_t)(kb + ty + i) * 256 + (nb + tx)];
    __syncthreads();
    __half* dst = g_WtH[blockIdx.z];
#pragma unroll
    for (int i = 0; i < 32; i += 8)
        dst[(size_t)(nb + ty + i) * 256 + (kb + tx)] = __float2half_rn(t[tx][ty + i]);
}

// ---------------------------------------------------------------------------
// main fused kernel: one CTA = 64 rows end-to-end; warp = 64M x 32N tile
// ---------------------------------------------------------------------------
__global__ void __launch_bounds__(THREADS, 2) mlp_kernel(
    const float* __restrict__ coords,
    const float* __restrict__ W1, const float* __restrict__ b1,
    const float* __restrict__ b2, const float* __restrict__ b3,
    const float* __restrict__ b4, const float* __restrict__ b5,
    const float* __restrict__ W6, const float* __restrict__ b6,
    float* __restrict__ out) {
    extern __shared__ __align__(128) char smem[];
    const uint32_t sb = smem_u32(smem);
    const int tid = threadIdx.x;
    const int wid = tid >> 5;
    const int lid = tid & 31;
    const int g = lid >> 2;          // 0..7
    const int t = lid & 3;           // 0..3
    const int nbase = wid * 32;      // this warp's private N slice
    const int row_base = blockIdx.x * TILE_M;

    float* sW1 = (float*)(smem + SM_W1);
    float* sB1 = (float*)(smem + SM_B1);
    float* sB2 = (float*)(smem + SM_B2);
    float* sB3 = (float*)(smem + SM_B3);
    float* sB4 = (float*)(smem + SM_B4);
    float* sB5 = (float*)(smem + SM_B5);
    float* sW6 = (float*)(smem + SM_W6);
    float* sB6 = (float*)(smem + SM_B6);
    float* sPart = (float*)(smem + SM_PART);
    __half* sA = (__half*)(smem + SM_A);

    // stage small params
    sW1[tid]       = W1[tid];
    sW1[tid + 256] = W1[tid + 256];
    sB1[tid] = b1[tid];
    sB2[tid] = b2[tid];
    sB3[tid] = b3[tid];
    sB4[tid] = b4[tid];
    sB5[tid] = b5[tid];
    sW6[tid] = W6[tid];
    if (tid == 0) sB6[0] = b6[0];

    // warp-private double-buffered B chunk bases
    const uint32_t buf0 = sb + SM_B + (uint32_t)wid * 8192;
    const uint32_t buf1 = buf0 + 4096;

    // prologue: chunks 0,1 of layer 2
    load_wchunk(buf0, g_WtH[0], nbase, 0, lid);
    load_wchunk(buf1, g_WtH[0], nbase, 1, lid);

    __syncthreads();

    // ---- Layer 1 (fan-in 2, FFMA) -> sA (fp16) ----
    {
        const int row = tid >> 2;
        const int j0  = (tid & 3) * 64;
        const float2 c = *(const float2*)(coords + 2 * (size_t)(row_base + row));
        __half* dst = sA + (size_t)row * A_STRIDE;
#pragma unroll
        for (int j = 0; j < 64; j += 2) {
            const int jj = j0 + j;
            float v0 = fmaxf(fmaf(c.x, sW1[jj + 0], fmaf(c.y, sW1[256 + jj + 0], sB1[jj + 0])), 0.f);
            float v1 = fmaxf(fmaf(c.x, sW1[jj + 1], fmaf(c.y, sW1[256 + jj + 1], sB1[jj + 1])), 0.f);
            *(__half2*)(dst + jj) = __floats2half2_rn(v0, v1);
        }
    }
    __syncthreads();

    // ldmatrix lane-address bases
    // A: lanes 0-7 rows 0..7 @k | 8-15 rows 8..15 @k | 16-23 rows 0..7 @k+8 | 24-31 rows 8..15 @k+8
    const uint32_t aA = sb + SM_A +
        (uint32_t)(((lid & 15) * A_STRIDE + ((lid & 16) ? 8 : 0)) * 2);
    // B: swizzled rows. lane -> row r(np), segment s = 2*ks + b8, phys seg = s ^ (r&7)
    const int brow = (lid & 7) + ((lid & 16) ? 8 : 0);   // row within 16-block
    const uint32_t bOff0 = (uint32_t)brow * 128;          // np=0 rows 0..15
    const uint32_t bOff1 = bOff0 + 16 * 128;              // np=1 rows 16..31
    const uint32_t brx = (uint32_t)(brow & 7);
    const uint32_t b8 = (lid & 8) ? 1u : 0u;

    // ---- Layers 2..5 ----
#pragma unroll 1
    for (int l = 0; l < 4; l++) {
        float acc[4][4][4];
#pragma unroll
        for (int i = 0; i < 4; i++)
#pragma unroll
            for (int j = 0; j < 4; j++)
#pragma unroll
                for (int c = 0; c < 4; c++) acc[i][j][c] = 0.f;

#pragma unroll
        for (int c = 0; c < 4; c++) {
            if (l == 3 && c == 3) cp_wait0(); else cp_wait1();
            __syncwarp();

            const uint32_t buf = (c & 1) ? buf1 : buf0;
#pragma unroll
            for (int ks = 0; ks < 4; ks++) {
                const int k0 = c * 64 + ks * 16;      // halves within full K
                const uint32_t seg = (uint32_t)(2 * ks) + b8;
                const uint32_t soff = ((seg ^ brx) << 4);
                uint32_t b[2][4];
                LDMATRIX_X4(b[0][0], b[0][1], b[0][2], b[0][3], buf + bOff0 + soff);
                LDMATRIX_X4(b[1][0], b[1][1], b[1][2], b[1][3], buf + bOff1 + soff);
#pragma unroll
                for (int i = 0; i < 4; i++) {
                    uint32_t a[4];
                    const uint32_t addr = aA + (uint32_t)(i * 16 * A_STRIDE + k0) * 2;
                    LDMATRIX_X4(a[0], a[1], a[2], a[3], addr);
#pragma unroll
                    for (int j = 0; j < 4; j++)
                        mma_f16(acc[i][j], a, &b[j >> 1][(j & 1) * 2]);
                }
            }

            // prefetch chunk f+2 (flat index) into the buffer just consumed
            const int f = l * 4 + c;
            if (f < 14) {
                const int q = f + 2;
                load_wchunk((c & 1) ? buf1 : buf0, g_WtH[q >> 2], nbase,
                            q & 3, lid);
            }
        }

        __syncthreads();   // all warps done reading sA

        if (l < 3) {
            // epilogue: sA <- (half)relu(D + bias) for this warp's 32 cols
            const float* bias = (l == 0) ? sB2 : (l == 1) ? sB3 : sB4;
#pragma unroll
            for (int j = 0; j < 4; j++) {
                const int col = nbase + 8 * j + 2 * t;
                const float bs0 = bias[col], bs1 = bias[col + 1];
#pragma unroll
                for (int i = 0; i < 4; i++) {
                    const int row = 16 * i + g;
                    *(__half2*)(sA + (size_t)row * A_STRIDE + col) =
                        __floats2half2_rn(fmaxf(acc[i][j][0] + bs0, 0.f),
                                          fmaxf(acc[i][j][1] + bs1, 0.f));
                    *(__half2*)(sA + (size_t)(row + 8) * A_STRIDE + col) =
                        __floats2half2_rn(fmaxf(acc[i][j][2] + bs0, 0.f),
                                          fmaxf(acc[i][j][3] + bs1, 0.f));
                }
            }
            __syncthreads();
        } else {
            // ---- Layer 6: out = relu(D + b5) . W6 + b6 ----
            float r0[4] = {0.f, 0.f, 0.f, 0.f};
            float r1[4] = {0.f, 0.f, 0.f, 0.f};
#pragma unroll
            for (int j = 0; j < 4; j++) {
                const int col = nbase + 8 * j + 2 * t;
                const float w0 = sW6[col], w1 = sW6[col + 1];
                const float s0 = sB5[col], s1 = sB5[col + 1];
#pragma unroll
                for (int i = 0; i < 4; i++) {
                    r0[i] = fmaf(fmaxf(acc[i][j][0] + s0, 0.f), w0, r0[i]);
                    r0[i] = fmaf(fmaxf(acc[i][j][1] + s1, 0.f), w1, r0[i]);
                    r1[i] = fmaf(fmaxf(acc[i][j][2] + s0, 0.f), w0, r1[i]);
                    r1[i] = fmaf(fmaxf(acc[i][j][3] + s1, 0.f), w1, r1[i]);
                }
            }
#pragma unroll
            for (int d = 1; d <= 2; d <<= 1) {
#pragma unroll
                for (int i = 0; i < 4; i++) {
                    r0[i] += __shfl_xor_sync(0xFFFFFFFFu, r0[i], d);
                    r1[i] += __shfl_xor_sync(0xFFFFFFFFu, r1[i], d);
                }
            }
            if (t == 0) {
                float* part = sPart + wid * 64;
#pragma unroll
                for (int i = 0; i < 4; i++) {
                    part[16 * i + g]     = r0[i];
                    part[16 * i + g + 8] = r1[i];
                }
            }
            __syncthreads();
            if (tid < TILE_M) {
                float s = sB6[0];
#pragma unroll
                for (int w = 0; w < 8; w++) s += sPart[w * 64 + tid];
                out[row_base + tid] = s;
            }
        }
    }
}

// ---------------------------------------------------------------------------
extern "C" void kernel_launch(void* const* d_in, const int* in_sizes, int n_in,
                              void* d_out, int out_size) {
    const float* coords = (const float*)d_in[0];
    const float* W1 = (const float*)d_in[1];
    const float* b1 = (const float*)d_in[2];
    const float* W2 = (const float*)d_in[3];
    const float* b2 = (const float*)d_in[4];
    const float* W3 = (const float*)d_in[5];
    const float* b3 = (const float*)d_in[6];
    const float* W4 = (const float*)d_in[7];
    const float* b4 = (const float*)d_in[8];
    const float* W5 = (const float*)d_in[9];
    const float* b5 = (const float*)d_in[10];
    const float* W6 = (const float*)d_in[11];
    const float* b6 = (const float*)d_in[12];
    float* out = (float*)d_out;

    const int n = in_sizes[0] / 2;  // rows

    transpose_w_kernel<<<dim3(NDIM / 32, KDIM / 32, 4), dim3(32, 8)>>>(W2, W3, W4, W5);

    cudaFuncSetAttribute(mlp_kernel, cudaFuncAttributeMaxDynamicSharedMemorySize, SMEM_TOTAL);
    mlp_kernel<<<n / TILE_M, THREADS, SMEM_TOTAL>>>(coords, W1, b1, b2, b3, b4, b5,
                                                    W6, b6, out);
}

// round 6
// speedup vs baseline: 1.1633x; 1.1633x over previous
#include <cuda_runtime.h>
#include <cuda_fp16.h>
#include <cstdint>

// ---------------------------------------------------------------------------
// SmallMLP_INR: fused 6-layer MLP, base-target ISA (compute_103-safe).
// Register-resident activations: each warp owns a 16-row M-slice and computes
// all 256 N columns; the mma C fragment layout IS the next layer's A fragment
// layout, so activations never touch SMEM. Only weights stream through a
// 4-slot SMEM ring (cp.async, XOR-swizzled), shared by all warps.
// ---------------------------------------------------------------------------

#define THREADS 256
#define TILE_M  128
#define KDIM    256
#define NDIM    256

// SMEM layout (bytes)
#define SM_W1    0        // 512 f32 = 2048
#define SM_B1    2048
#define SM_B2    3072
#define SM_B3    4096
#define SM_B4    5120
#define SM_B5    6144
#define SM_W6    7168
#define SM_B6    8192
#define SM_RING  9216     // 4 slots * 32768 = 131072
#define SMEM_TOTAL 140288

// Pre-transposed fp16 weights: g_WtH[l][n*256 + k] = (half)W_{l+2}[k][n]
__device__ __half g_WtH[4][KDIM * NDIM];

// ---------------------------------------------------------------------------
__device__ __forceinline__ uint32_t smem_u32(const void* p) {
    uint32_t a;
    asm("{ .reg .u64 t; cvta.to.shared.u64 t, %1; cvt.u32.u64 %0, t; }" : "=r"(a) : "l"(p));
    return a;
}

__device__ __forceinline__ void mma_f16(float* c, const uint32_t* a,
                                        uint32_t b0, uint32_t b1) {
    asm volatile(
        "mma.sync.aligned.m16n8k16.row.col.f32.f16.f16.f32 "
        "{%0,%1,%2,%3}, {%4,%5,%6,%7}, {%8,%9}, {%0,%1,%2,%3};\n"
        : "+f"(c[0]), "+f"(c[1]), "+f"(c[2]), "+f"(c[3])
        : "r"(a[0]), "r"(a[1]), "r"(a[2]), "r"(a[3]), "r"(b0), "r"(b1));
}

#define LDMATRIX_X4(r0, r1, r2, r3, addr) \
    asm volatile("ldmatrix.sync.aligned.m8n8.x4.shared.b16 {%0,%1,%2,%3}, [%4];" \
                 : "=r"(r0), "=r"(r1), "=r"(r2), "=r"(r3) : "r"(addr))

__device__ __forceinline__ void cp_async16(uint32_t dst, const void* src) {
    asm volatile("cp.async.cg.shared.global [%0], [%1], 16;" :: "r"(dst), "l"(src) : "memory");
}
__device__ __forceinline__ void cp_commit() { asm volatile("cp.async.commit_group;" ::: "memory"); }
__device__ __forceinline__ void cp_wait2()  { asm volatile("cp.async.wait_group 2;" ::: "memory"); }
__device__ __forceinline__ void cp_wait1()  { asm volatile("cp.async.wait_group 1;" ::: "memory"); }
__device__ __forceinline__ void cp_wait0()  { asm volatile("cp.async.wait_group 0;" ::: "memory"); }

__device__ __forceinline__ uint32_t pack2(float x, float y) {
    __half2 h = __floats2half2_rn(x, y);
    return *reinterpret_cast<uint32_t*>(&h);
}

// CTA-wide: load one 256x64 weight chunk (32KB) into a ring slot.
// Thread tid loads n-row tid (128B) as 8 XOR-swizzled 16B segments.
__device__ __forceinline__ void load_chunk(uint32_t slot, const __half* Wt,
                                           int c, int tid) {
    const uint32_t dstrow = slot + (uint32_t)tid * 128;
    const uint32_t rx = (uint32_t)(tid & 7);
    const __half* src = Wt + (size_t)tid * KDIM + c * 64;
#pragma unroll
    for (uint32_t j = 0; j < 8; j++)
        cp_async16(dstrow + ((j ^ rx) << 4), src + j * 8);
    cp_commit();
}

// ---------------------------------------------------------------------------
// weight pre-transpose + fp16 round
// ---------------------------------------------------------------------------
__global__ void transpose_w_kernel(const float* __restrict__ W2, const float* __restrict__ W3,
                                   const float* __restrict__ W4, const float* __restrict__ W5) {
    __shared__ float t[32][33];
    const float* W = (blockIdx.z == 0) ? W2 : (blockIdx.z == 1) ? W3
                   : (blockIdx.z == 2) ? W4 : W5;
    const int nb = blockIdx.x * 32, kb = blockIdx.y * 32;
    const int tx = threadIdx.x, ty = threadIdx.y;
#pragma unroll
    for (int i = 0; i < 32; i += 8)
        t[ty + i][tx] = W[(size_t)(kb + ty + i) * 256 + (nb + tx)];
    __syncthreads();
    __half* dst = g_WtH[blockIdx.z];
#pragma unroll
    for (int i = 0; i < 32; i += 8)
        dst[(size_t)(nb + ty + i) * 256 + (kb + tx)] = __float2half_rn(t[tx][ty + i]);
}

// ---------------------------------------------------------------------------
// main fused kernel: warp = 16 rows x 256 cols, activations in registers
// ---------------------------------------------------------------------------
__global__ void __launch_bounds__(THREADS, 1) mlp_kernel(
    const float* __restrict__ coords,
    const float* __restrict__ W1, const float* __restrict__ b1,
    const float* __restrict__ b2, const float* __restrict__ b3,
    const float* __restrict__ b4, const float* __restrict__ b5,
    const float* __restrict__ W6, const float* __restrict__ b6,
    float* __restrict__ out) {
    extern __shared__ __align__(128) char smem[];
    const uint32_t sb = smem_u32(smem);
    const int tid = threadIdx.x;
    const int wid = tid >> 5;
    const int lid = tid & 31;
    const int g = lid >> 2;          // 0..7
    const int t = lid & 3;           // 0..3
    const int row_base = blockIdx.x * TILE_M + wid * 16;

    float* sW1 = (float*)(smem + SM_W1);
    float* sB1 = (float*)(smem + SM_B1);
    float* sB2 = (float*)(smem + SM_B2);
    float* sB3 = (float*)(smem + SM_B3);
    float* sB4 = (float*)(smem + SM_B4);
    float* sB5 = (float*)(smem + SM_B5);
    float* sW6 = (float*)(smem + SM_W6);
    float* sB6 = (float*)(smem + SM_B6);
    const uint32_t rb = sb + SM_RING;

    // stage small params
    sW1[tid]       = W1[tid];
    sW1[tid + 256] = W1[tid + 256];
    sB1[tid] = b1[tid];
    sB2[tid] = b2[tid];
    sB3[tid] = b3[tid];
    sB4[tid] = b4[tid];
    sB5[tid] = b5[tid];
    sW6[tid] = W6[tid];
    if (tid == 0) sB6[0] = b6[0];

    // prologue: prefetch first 3 weight chunks of layer 2
    load_chunk(rb,         g_WtH[0], 0, tid);
    load_chunk(rb + 32768, g_WtH[0], 1, tid);
    load_chunk(rb + 65536, g_WtH[0], 2, tid);

    __syncthreads();

    // ---- Layer 1: coords -> A fragments (registers) ----
    // afr[kk][0]=(row g, k-lo) afr[kk][1]=(row g+8, k-lo)
    // afr[kk][2]=(row g, k-hi) afr[kk][3]=(row g+8, k-hi)
    uint32_t afr[16][4];
    {
        const float2 ca = *(const float2*)(coords + 2 * (size_t)(row_base + g));
        const float2 cb = *(const float2*)(coords + 2 * (size_t)(row_base + g + 8));
#pragma unroll
        for (int kk = 0; kk < 16; kk++) {
#pragma unroll
            for (int h = 0; h < 2; h++) {
                const int c0 = 16 * kk + 8 * h + 2 * t;
                const float w00 = sW1[c0],     w01 = sW1[c0 + 1];
                const float w10 = sW1[256 + c0], w11 = sW1[256 + c0 + 1];
                const float bb0 = sB1[c0], bb1 = sB1[c0 + 1];
                const float a00 = fmaxf(fmaf(ca.x, w00, fmaf(ca.y, w10, bb0)), 0.f);
                const float a01 = fmaxf(fmaf(ca.x, w01, fmaf(ca.y, w11, bb1)), 0.f);
                const float a10 = fmaxf(fmaf(cb.x, w00, fmaf(cb.y, w10, bb0)), 0.f);
                const float a11 = fmaxf(fmaf(cb.x, w01, fmaf(cb.y, w11, bb1)), 0.f);
                afr[kk][2 * h]     = pack2(a00, a01);
                afr[kk][2 * h + 1] = pack2(a10, a11);
            }
        }
    }

    // ldmatrix B lane addressing (XOR-swizzled 128B rows)
    const uint32_t laneB = (uint32_t)(((lid & 7) + ((lid & 16) ? 8 : 0)) * 128);
    const uint32_t brx = (uint32_t)(lid & 7);
    const uint32_t b8 = (uint32_t)((lid >> 3) & 1);

    // ---- Layers 2..5 ----
#pragma unroll 1
    for (int l = 0; l < 4; l++) {
        float acc[32][4];
#pragma unroll
        for (int j = 0; j < 32; j++)
#pragma unroll
            for (int c = 0; c < 4; c++) acc[j][c] = 0.f;

#pragma unroll
        for (int c = 0; c < 4; c++) {
            // flat chunk f = 4l + c; ring slot f & 3 == c
            if (l == 3) {
                if (c == 2) cp_wait1();
                else if (c == 3) cp_wait0();
                else cp_wait2();
            } else {
                cp_wait2();
            }
            __syncthreads();

            // prefetch chunk f+3 into the slot freed by chunk f-1
            if (l * 4 + c + 3 < 16) {
                const int q = l * 4 + c + 3;
                load_chunk(rb + (uint32_t)(q & 3) * 32768, g_WtH[q >> 2],
                           q & 3, tid);
            }

            const uint32_t slot = rb + (uint32_t)c * 32768;
#pragma unroll
            for (int ks = 0; ks < 4; ks++) {
                const uint32_t soff = ((((uint32_t)(2 * ks) + b8) ^ brx) << 4);
                const int kk = c * 4 + ks;
#pragma unroll
                for (int jj = 0; jj < 16; jj++) {
                    uint32_t b0, b1, b2, b3;
                    LDMATRIX_X4(b0, b1, b2, b3,
                                slot + (uint32_t)jj * 2048 + laneB + soff);
                    mma_f16(acc[2 * jj],     afr[kk], b0, b1);
                    mma_f16(acc[2 * jj + 1], afr[kk], b2, b3);
                }
            }
        }

        if (l < 3) {
            // register epilogue: acc -> next-layer A fragments
            const float* bias = (l == 0) ? sB2 : (l == 1) ? sB3 : sB4;
#pragma unroll
            for (int kk = 0; kk < 16; kk++) {
                const int j0 = 2 * kk, j1 = 2 * kk + 1;
                const float b00 = bias[8 * j0 + 2 * t], b01 = bias[8 * j0 + 2 * t + 1];
                const float b10 = bias[8 * j1 + 2 * t], b11 = bias[8 * j1 + 2 * t + 1];
                afr[kk][0] = pack2(fmaxf(acc[j0][0] + b00, 0.f),
                                   fmaxf(acc[j0][1] + b01, 0.f));
                afr[kk][1] = pack2(fmaxf(acc[j0][2] + b00, 0.f),
                                   fmaxf(acc[j0][3] + b01, 0.f));
                afr[kk][2] = pack2(fmaxf(acc[j1][0] + b10, 0.f),
                                   fmaxf(acc[j1][1] + b11, 0.f));
                afr[kk][3] = pack2(fmaxf(acc[j1][2] + b10, 0.f),
                                   fmaxf(acc[j1][3] + b11, 0.f));
            }
        } else {
            // ---- Layer 6: out = relu(D + b5) . W6 + b6 ----
            float rg = 0.f, rg8 = 0.f;
#pragma unroll
            for (int j = 0; j < 32; j++) {
                const int col = 8 * j + 2 * t;
                const float w0 = sW6[col], w1 = sW6[col + 1];
                const float s0 = sB5[col], s1 = sB5[col + 1];
                rg  = fmaf(fmaxf(acc[j][0] + s0, 0.f), w0, rg);
                rg  = fmaf(fmaxf(acc[j][1] + s1, 0.f), w1, rg);
                rg8 = fmaf(fmaxf(acc[j][2] + s0, 0.f), w0, rg8);
                rg8 = fmaf(fmaxf(acc[j][3] + s1, 0.f), w1, rg8);
            }
            rg  += __shfl_xor_sync(0xFFFFFFFFu, rg, 1);
            rg  += __shfl_xor_sync(0xFFFFFFFFu, rg, 2);
            rg8 += __shfl_xor_sync(0xFFFFFFFFu, rg8, 1);
            rg8 += __shfl_xor_sync(0xFFFFFFFFu, rg8, 2);
            if (t == 0) {
                const float bb = sB6[0];
                out[row_base + g]     = rg + bb;
                out[row_base + g + 8] = rg8 + bb;
            }
        }
    }
}

// ---------------------------------------------------------------------------
extern "C" void kernel_launch(void* const* d_in, const int* in_sizes, int n_in,
                              void* d_out, int out_size) {
    const float* coords = (const float*)d_in[0];
    const float* W1 = (const float*)d_in[1];
    const float* b1 = (const float*)d_in[2];
    const float* W2 = (const float*)d_in[3];
    const float* b2 = (const float*)d_in[4];
    const float* W3 = (const float*)d_in[5];
    const float* b3 = (const float*)d_in[6];
    const float* W4 = (const float*)d_in[7];
    const float* b4 = (const float*)d_in[8];
    const float* W5 = (const float*)d_in[9];
    const float* b5 = (const float*)d_in[10];
    const float* W6 = (const float*)d_in[11];
    const float* b6 = (const float*)d_in[12];
    float* out = (float*)d_out;

    const int n = in_sizes[0] / 2;  // rows

    transpose_w_kernel<<<dim3(NDIM / 32, KDIM / 32, 4), dim3(32, 8)>>>(W2, W3, W4, W5);

    cudaFuncSetAttribute(mlp_kernel, cudaFuncAttributeMaxDynamicSharedMemorySize, SMEM_TOTAL);
    mlp_kernel<<<n / TILE_M, THREADS, SMEM_TOTAL>>>(coords, W1, b1, b2, b3, b4, b5,
                                                    W6, b6, out);
}

// round 7
// speedup vs baseline: 1.2289x; 1.0564x over previous
#include <cuda_runtime.h>
#include <cuda_fp16.h>
#include <cstdint>

// ---------------------------------------------------------------------------
// SmallMLP_INR: fused 6-layer MLP, base-target ISA (compute_103-safe).
// fp16 m16n8k16 mma.sync + ldmatrix. 64x64 warp tiles (minimal LDS/MAC),
// flat 16-chunk cp.async ring (4 slots, depth-3), one barrier per chunk.
// ---------------------------------------------------------------------------

#define THREADS 256
#define TILE_M  128
#define KDIM    256
#define NDIM    256

#define A_STRIDE 264   // halves; 528B rows -> ldmatrix conflict-free
#define B_STRIDE 72    // halves; 144B rows -> ldmatrix conflict-free
#define SLOT_BYTES 36864   // 256 * 72 * 2

// SMEM layout (bytes)
#define SM_W1    0        // 512 f32
#define SM_B1    2048
#define SM_B2    3072
#define SM_B3    4096
#define SM_B4    5120
#define SM_B5    6144
#define SM_W6    7168
#define SM_B6    8192
#define SM_PART  8208     // 4*128 f32 = 2048
#define SM_A     10496    // 128*264*2 = 67584
#define SM_RING  78080    // 4 * 36864 = 147456
#define SMEM_TOTAL 225536

// Pre-transposed fp16 weights: g_WtH[l][n*256 + k] = (half)W_{l+2}[k][n]
__device__ __half g_WtH[4][KDIM * NDIM];

// ---------------------------------------------------------------------------
__device__ __forceinline__ uint32_t smem_u32(const void* p) {
    uint32_t a;
    asm("{ .reg .u64 t; cvta.to.shared.u64 t, %1; cvt.u32.u64 %0, t; }" : "=r"(a) : "l"(p));
    return a;
}

__device__ __forceinline__ void mma_f16(float* c, const uint32_t* a, const uint32_t* b) {
    asm volatile(
        "mma.sync.aligned.m16n8k16.row.col.f32.f16.f16.f32 "
        "{%0,%1,%2,%3}, {%4,%5,%6,%7}, {%8,%9}, {%0,%1,%2,%3};\n"
        : "+f"(c[0]), "+f"(c[1]), "+f"(c[2]), "+f"(c[3])
        : "r"(a[0]), "r"(a[1]), "r"(a[2]), "r"(a[3]), "r"(b[0]), "r"(b[1]));
}

#define LDMATRIX_X4(r0, r1, r2, r3, addr) \
    asm volatile("ldmatrix.sync.aligned.m8n8.x4.shared.b16 {%0,%1,%2,%3}, [%4];" \
                 : "=r"(r0), "=r"(r1), "=r"(r2), "=r"(r3) : "r"(addr))

__device__ __forceinline__ void cp_async16(uint32_t dst, const void* src) {
    asm volatile("cp.async.cg.shared.global [%0], [%1], 16;" :: "r"(dst), "l"(src) : "memory");
}
__device__ __forceinline__ void cp_commit() { asm volatile("cp.async.commit_group;" ::: "memory"); }
__device__ __forceinline__ void cp_wait2()  { asm volatile("cp.async.wait_group 2;" ::: "memory"); }
__device__ __forceinline__ void cp_wait1()  { asm volatile("cp.async.wait_group 1;" ::: "memory"); }
__device__ __forceinline__ void cp_wait0()  { asm volatile("cp.async.wait_group 0;" ::: "memory"); }

// CTA-wide: one 256x64 weight chunk (32KB) into a ring slot (padded rows).
// Thread tid loads n-row tid: 64 halves = 8 x 16B cp.async.
__device__ __forceinline__ void load_chunk(uint32_t slot, const __half* Wt,
                                           int c, int tid) {
    uint32_t dst = slot + (uint32_t)tid * (B_STRIDE * 2);
    const __half* src = Wt + (size_t)tid * KDIM + c * 64;
#pragma unroll
    for (int j = 0; j < 8; j++)
        cp_async16(dst + j * 16, src + j * 8);
    cp_commit();
}

// ---------------------------------------------------------------------------
// weight pre-transpose + fp16 round
// ---------------------------------------------------------------------------
__global__ void transpose_w_kernel(const float* __restrict__ W2, const float* __restrict__ W3,
                                   const float* __restrict__ W4, const float* __restrict__ W5) {
    __shared__ float t[32][33];
    const float* W = (blockIdx.z == 0) ? W2 : (blockIdx.z == 1) ? W3
                   : (blockIdx.z == 2) ? W4 : W5;
    const int nb = blockIdx.x * 32, kb = blockIdx.y * 32;
    const int tx = threadIdx.x, ty = threadIdx.y;
#pragma unroll
    for (int i = 0; i < 32; i += 8)
        t[ty + i][tx] = W[(size_t)(kb + ty + i) * 256 + (nb + tx)];
    __syncthreads();
    __half* dst = g_WtH[blockIdx.z];
#pragma unroll
    for (int i = 0; i < 32; i += 8)
        dst[(size_t)(nb + ty + i) * 256 + (kb + tx)] = __float2half_rn(t[tx][ty + i]);
}

// ---------------------------------------------------------------------------
// main fused kernel: one CTA = 128 rows; warp = 64M x 64N tile
// ---------------------------------------------------------------------------
__global__ void __launch_bounds__(THREADS, 1) mlp_kernel(
    const float* __restrict__ coords,
    const float* __restrict__ W1, const float* __restrict__ b1,
    const float* __restrict__ b2, const float* __restrict__ b3,
    const float* __restrict__ b4, const float* __restrict__ b5,
    const float* __restrict__ W6, const float* __restrict__ b6,
    float* __restrict__ out) {
    extern __shared__ __align__(128) char smem[];
    const uint32_t sb = smem_u32(smem);
    const int tid = threadIdx.x;
    const int wid = tid >> 5;
    const int lid = tid & 31;
    const int g = lid >> 2;
    const int t = lid & 3;
    const int mrow = (wid & 1) * 64;      // 2 M-slots of 64 rows
    const int ncol = (wid >> 1) * 64;     // 4 N-slots of 64 cols
    const int row_base = blockIdx.x * TILE_M;

    float* sW1 = (float*)(smem + SM_W1);
    float* sB1 = (float*)(smem + SM_B1);
    float* sB2 = (float*)(smem + SM_B2);
    float* sB3 = (float*)(smem + SM_B3);
    float* sB4 = (float*)(smem + SM_B4);
    float* sB5 = (float*)(smem + SM_B5);
    float* sW6 = (float*)(smem + SM_W6);
    float* sB6 = (float*)(smem + SM_B6);
    float* sPart = (float*)(smem + SM_PART);
    __half* sA = (__half*)(smem + SM_A);
    const uint32_t rb = sb + SM_RING;

    // stage small params
    sW1[tid]       = W1[tid];
    sW1[tid + 256] = W1[tid + 256];
    sB1[tid] = b1[tid];
    sB2[tid] = b2[tid];
    sB3[tid] = b3[tid];
    sB4[tid] = b4[tid];
    sB5[tid] = b5[tid];
    sW6[tid] = W6[tid];
    if (tid == 0) sB6[0] = b6[0];

    // prologue: prefetch chunks 0..2 of layer 2 (slots 0..2)
    load_chunk(rb,                 g_WtH[0], 0, tid);
    load_chunk(rb + SLOT_BYTES,    g_WtH[0], 1, tid);
    load_chunk(rb + 2 * SLOT_BYTES, g_WtH[0], 2, tid);

    __syncthreads();

    // ---- Layer 1 (fan-in 2, FFMA) -> sA (fp16) ----
    {
        const int row = tid >> 1;
        const int j0  = (tid & 1) * 128;
        const float2 c = *(const float2*)(coords + 2 * (size_t)(row_base + row));
        __half* dst = sA + (size_t)row * A_STRIDE;
#pragma unroll
        for (int j = 0; j < 128; j += 2) {
            const int jj = j0 + j;
            float v0 = fmaxf(fmaf(c.x, sW1[jj + 0], fmaf(c.y, sW1[256 + jj + 0], sB1[jj + 0])), 0.f);
            float v1 = fmaxf(fmaf(c.x, sW1[jj + 1], fmaf(c.y, sW1[256 + jj + 1], sB1[jj + 1])), 0.f);
            *(__half2*)(dst + jj) = __floats2half2_rn(v0, v1);
        }
    }

    // ldmatrix lane-address bases
    // A: lanes 0-7 rows 0..7 @k | 8-15 rows 8..15 @k | 16-23 rows 0..7 @k+8 | 24-31 rows 8..15 @k+8
    const uint32_t aA = sb + SM_A +
        (uint32_t)(((mrow + (lid & 15)) * A_STRIDE + ((lid & 16) ? 8 : 0)) * 2);
    // B: lanes 0-7 n+0..7 @k | 8-15 n+0..7 @k+8 | 16-23 n+8..15 @k | 24-31 n+8..15 @k+8
    const uint32_t bOff =
        (uint32_t)((ncol + (lid & 7) + ((lid & 16) ? 8 : 0)) * B_STRIDE * 2 +
                   ((lid & 8) ? 16 : 0));

    // ---- Layers 2..5: flat 16-chunk pipeline, slot index == c ----
#pragma unroll 1
    for (int l = 0; l < 4; l++) {
        float acc[4][8][4];
#pragma unroll
        for (int i = 0; i < 4; i++)
#pragma unroll
            for (int j = 0; j < 8; j++)
#pragma unroll
                for (int c = 0; c < 4; c++) acc[i][j][c] = 0.f;

#pragma unroll
        for (int c = 0; c < 4; c++) {
            if (l == 3 && c == 2)      cp_wait1();
            else if (l == 3 && c == 3) cp_wait0();
            else                       cp_wait2();
            __syncthreads();

            const uint32_t bB = rb + (uint32_t)c * SLOT_BYTES + bOff;
#pragma unroll
            for (int ks = 0; ks < 4; ks++) {
                const int k0 = c * 64 + ks * 16;   // global k (halves)
                uint32_t b[4][4];
#pragma unroll
                for (int jp = 0; jp < 4; jp++) {
                    const uint32_t addr = bB + (uint32_t)(jp * 16 * B_STRIDE + ks * 16) * 2;
                    LDMATRIX_X4(b[jp][0], b[jp][1], b[jp][2], b[jp][3], addr);
                }
#pragma unroll
                for (int i = 0; i < 4; i++) {
                    uint32_t a[4];
                    const uint32_t addr = aA + (uint32_t)(i * 16 * A_STRIDE + k0) * 2;
                    LDMATRIX_X4(a[0], a[1], a[2], a[3], addr);
#pragma unroll
                    for (int j = 0; j < 8; j++)
                        mma_f16(acc[i][j], a, &b[j >> 1][(j & 1) * 2]);
                }
            }

            // prefetch chunk f+3 into slot (c+3)&3 (freed by chunk f-1)
            const int q = l * 4 + c + 3;
            if (q < 16)
                load_chunk(rb + (uint32_t)(q & 3) * SLOT_BYTES, g_WtH[q >> 2],
                           q & 3, tid);
        }

        __syncthreads();   // all warps done reading sA

        if (l < 3) {
            // epilogue: sA <- (half)relu(D + bias) for this warp's 64x64 tile
            const float* bias = (l == 0) ? sB2 : (l == 1) ? sB3 : sB4;
#pragma unroll
            for (int j = 0; j < 8; j++) {
                const int col = ncol + 8 * j + 2 * t;
                const float bs0 = bias[col], bs1 = bias[col + 1];
#pragma unroll
                for (int i = 0; i < 4; i++) {
                    const int row = mrow + 16 * i + g;
                    *(__half2*)(sA + (size_t)row * A_STRIDE + col) =
                        __floats2half2_rn(fmaxf(acc[i][j][0] + bs0, 0.f),
                                          fmaxf(acc[i][j][1] + bs1, 0.f));
                    *(__half2*)(sA + (size_t)(row + 8) * A_STRIDE + col) =
                        __floats2half2_rn(fmaxf(acc[i][j][2] + bs0, 0.f),
                                          fmaxf(acc[i][j][3] + bs1, 0.f));
                }
            }
            // next chunk's __syncthreads orders these writes before reads
        } else {
            // ---- Layer 6: out = relu(D + b5) . W6 + b6 ----
            float r0[4] = {0.f, 0.f, 0.f, 0.f};
            float r1[4] = {0.f, 0.f, 0.f, 0.f};
#pragma unroll
            for (int j = 0; j < 8; j++) {
                const int col = ncol + 8 * j + 2 * t;
                const float w0 = sW6[col], w1 = sW6[col + 1];
                const float s0 = sB5[col], s1 = sB5[col + 1];
#pragma unroll
                for (int i = 0; i < 4; i++) {
                    r0[i] = fmaf(fmaxf(acc[i][j][0] + s0, 0.f), w0, r0[i]);
                    r0[i] = fmaf(fmaxf(acc[i][j][1] + s1, 0.f), w1, r0[i]);
                    r1[i] = fmaf(fmaxf(acc[i][j][2] + s0, 0.f), w0, r1[i]);
                    r1[i] = fmaf(fmaxf(acc[i][j][3] + s1, 0.f), w1, r1[i]);
                }
            }
#pragma unroll
            for (int d = 1; d <= 2; d <<= 1) {
#pragma unroll
                for (int i = 0; i < 4; i++) {
                    r0[i] += __shfl_xor_sync(0xFFFFFFFFu, r0[i], d);
                    r1[i] += __shfl_xor_sync(0xFFFFFFFFu, r1[i], d);
                }
            }
            if (t == 0) {
                float* part = sPart + (wid >> 1) * 128;
#pragma unroll
                for (int i = 0; i < 4; i++) {
                    part[mrow + 16 * i + g]     = r0[i];
                    part[mrow + 16 * i + g + 8] = r1[i];
                }
            }
            __syncthreads();
            if (tid < TILE_M)
                out[row_base + tid] = sPart[tid] + sPart[128 + tid] +
                                      sPart[256 + tid] + sPart[384 + tid] + sB6[0];
        }
    }
}

// ---------------------------------------------------------------------------
extern "C" void kernel_launch(void* const* d_in, const int* in_sizes, int n_in,
                              void* d_out, int out_size) {
    const float* coords = (const float*)d_in[0];
    const float* W1 = (const float*)d_in[1];
    const float* b1 = (const float*)d_in[2];
    const float* W2 = (const float*)d_in[3];
    const float* b2 = (const float*)d_in[4];
    const float* W3 = (const float*)d_in[5];
    const float* b3 = (const float*)d_in[6];
    const float* W4 = (const float*)d_in[7];
    const float* b4 = (const float*)d_in[8];
    const float* W5 = (const float*)d_in[9];
    const float* b5 = (const float*)d_in[10];
    const float* W6 = (const float*)d_in[11];
    const float* b6 = (const float*)d_in[12];
    float* out = (float*)d_out;

    const int n = in_sizes[0] / 2;  // rows

    transpose_w_kernel<<<dim3(NDIM / 32, KDIM / 32, 4), dim3(32, 8)>>>(W2, W3, W4, W5);

    cudaFuncSetAttribute(mlp_kernel, cudaFuncAttributeMaxDynamicSharedMemorySize, SMEM_TOTAL);
    mlp_kernel<<<n / TILE_M, THREADS, SMEM_TOTAL>>>(coords, W1, b1, b2, b3, b4, b5,
                                                    W6, b6, out);
}